// round 14
// baseline (speedup 1.0000x reference)
#include <cuda_runtime.h>
#include <math.h>
#include <stdint.h>

#define BB 16
#define TT 16
#define LL 128
#define XX 256
#define HH 512
#define YY 256
#define RCTA 8
#define TPB 512

__device__ __align__(16) float g_b1[BB * HH];
__device__ __align__(16) float g_b2[BB * HH];
__device__ __align__(16) float g_b3[BB * HH];
__device__ __align__(16) float g_w2T[HH * HH];
__device__ __align__(16) float g_w3T[HH * HH];
__device__ __align__(16) float g_w4T[HH * YY];
__device__ __align__(16) float g_h1A[BB * TT * HH];
__device__ __align__(16) float g_h2A[BB * TT * HH];
__device__ __align__(16) float g_h3A[BB * TT * HH];
__device__ __align__(16) float g_hgA[BB * TT * HH];
__device__ __align__(16) float g_dz1A[BB * TT * HH];
__device__ __align__(16) float g_dz2A[BB * TT * HH];
__device__ __align__(16) float g_dz3A[BB * TT * HH];
__device__ __align__(16) float g_dlA[BB * TT * YY];
__device__ __align__(16) float g_xg[BB * TT * TT];
__device__ __align__(16) float g_ea[BB * LL * HH];
__device__ __align__(16) float g_eb[BB * LL * HH];
__device__ __align__(16) float g_cf[BB * TT * LL];

__device__ __forceinline__ float warp_sum(float v) {
    v += __shfl_xor_sync(0xffffffffu, v, 16);
    v += __shfl_xor_sync(0xffffffffu, v, 8);
    v += __shfl_xor_sync(0xffffffffu, v, 4);
    v += __shfl_xor_sync(0xffffffffu, v, 2);
    v += __shfl_xor_sync(0xffffffffu, v, 1);
    return v;
}

__device__ __forceinline__ void csync() {
    asm volatile("barrier.cluster.arrive.aligned;" ::: "memory");
    asm volatile("barrier.cluster.wait.aligned;" ::: "memory");
}

__device__ __forceinline__ uint32_t s2u(const void* p) {
    return (uint32_t)__cvta_generic_to_shared(p);
}

__device__ __forceinline__ void st_cluster_f2(uint32_t saddr, int rank, float2 v) {
    uint32_t ra;
    unsigned long long u =
        ((unsigned long long)__float_as_uint(v.y) << 32) | __float_as_uint(v.x);
    asm volatile("mapa.shared::cluster.u32 %0, %1, %2;" : "=r"(ra) : "r"(saddr), "r"(rank));
    asm volatile("st.shared::cluster.b64 [%0], %1;" :: "r"(ra), "l"(u) : "memory");
}

// packed fp32x2 FMA on persistent 64-bit accumulators (bit-identical to 2x fmaf)
__device__ __forceinline__ void ffma2l(unsigned long long& d, unsigned long long a,
                                       unsigned long long b) {
    asm("fma.rn.f32x2 %0, %1, %2, %0;" : "+l"(d) : "l"(a), "l"(b));
}
__device__ __forceinline__ float2 unpk(unsigned long long v) {
    float2 r;
    asm("mov.b64 {%0, %1}, %2;" : "=f"(r.x), "=f"(r.y) : "l"(v));
    return r;
}

// ---------------- pre-passes ----------------
__global__ void __launch_bounds__(256) k_tr(const float* __restrict__ fc2,
                                            const float* __restrict__ fc3,
                                            const float* __restrict__ fc4) {
    __shared__ float tile[32][33];
    int bid = blockIdx.x;
    const float* src;
    float* dst;
    int RS, CS;
    if (bid < 256) { src = fc2; dst = g_w2T; RS = HH; CS = HH; }
    else if (bid < 512) { src = fc3; dst = g_w3T; bid -= 256; RS = HH; CS = HH; }
    else { src = fc4; dst = g_w4T; bid -= 512; RS = YY; CS = HH; }
    int tpr = CS / 32;
    int r0 = (bid / tpr) * 32, c0 = (bid % tpr) * 32;
    int tx = threadIdx.x & 31, ty = threadIdx.x >> 5;
    for (int i = ty; i < 32; i += 8) tile[i][tx] = src[(size_t)(r0 + i) * CS + c0 + tx];
    __syncthreads();
    for (int i = ty; i < 32; i += 8) dst[(size_t)(c0 + i) * RS + r0 + tx] = tile[tx][i];
}

__global__ void __launch_bounds__(256) k_miscA(const float* __restrict__ b1,
                                               const float* __restrict__ b2,
                                               const float* __restrict__ b3) {
    int gt = blockIdx.x * blockDim.x + threadIdx.x;
    int NT = gridDim.x * blockDim.x;
    for (int i = gt; i < BB * HH; i += NT) {
        int k = i & (HH - 1);
        g_b1[i] = b1[k]; g_b2[i] = b2[k]; g_b3[i] = b3[k];
    }
}

__global__ void __launch_bounds__(256) k_miscB(const float* __restrict__ tx) {
    int gt = blockIdx.x * blockDim.x + threadIdx.x;
    int NT = gridDim.x * blockDim.x;
    int gw = gt >> 5, lane = gt & 31;
    for (int d = gw; d < BB * TT * TT; d += NT >> 5) {
        int b = d >> 8, s1 = (d >> 4) & 15, s2 = d & 15;
        const float4* xa = (const float4*)(tx + (size_t)(b * TT + s1) * XX);
        const float4* xb = (const float4*)(tx + (size_t)(b * TT + s2) * XX);
        float4 a = xa[lane], c = xb[lane];
        float acc = a.x * c.x + a.y * c.y + a.z * c.z + a.w * c.w;
        a = xa[lane + 32]; c = xb[lane + 32];
        acc += a.x * c.x + a.y * c.y + a.z * c.z + a.w * c.w;
        acc = warp_sum(acc);
        if (lane == 0) g_xg[d] = acc;
    }
}

// ---------------- train compute core (R13 winner, unchanged) -----------------
template <int K>
struct XR { float4 a[K / 128][2]; };

template <int K>
__device__ __forceinline__ void ldx(XR<K>& X, const float2* sv, int lane) {
#pragma unroll
    for (int i = 0; i < K / 128; i++) {
        const float4* p = (const float4*)(sv + 4 * lane + 128 * i);
        X.a[i][0] = p[0];
        X.a[i][1] = p[1];
    }
}

template <int K>
__device__ __forceinline__ float2 dotrow(const float* __restrict__ W, int n,
                                         const XR<K>& X, int lane) {
    float a0 = 0.f, a1 = 0.f, b0v = 0.f, b1v = 0.f;
#pragma unroll
    for (int i = 0; i < K / 128; i++) {
        float4 w = *(const float4*)(W + (size_t)n * K + 4 * lane + 128 * i);
        a0 = fmaf(w.x, X.a[i][0].x, a0); a1 = fmaf(w.x, X.a[i][0].y, a1);
        b0v = fmaf(w.y, X.a[i][0].z, b0v); b1v = fmaf(w.y, X.a[i][0].w, b1v);
        a0 = fmaf(w.z, X.a[i][1].x, a0); a1 = fmaf(w.z, X.a[i][1].y, a1);
        b0v = fmaf(w.w, X.a[i][1].z, b0v); b1v = fmaf(w.w, X.a[i][1].w, b1v);
    }
    return make_float2(a0 + b0v, a1 + b1v);
}

template <int NU, int NR>
__device__ __forceinline__ void corrw(const float* __restrict__ uA, int b0, int nb,
                                      const float* s_c, int t, int lane, float2* acc) {
    if (lane < t) {
        float cx = s_c[2 * lane], cy = s_c[2 * lane + 1];
        const float* u0 = uA + (size_t)(b0 * TT + lane) * NU + nb;
        const float* u1 = uA + (size_t)((b0 + 1) * TT + lane) * NU + nb;
#pragma unroll
        for (int j = 0; j < NR; j++) {
            acc[j].x = fmaf(-cx, u0[j], acc[j].x);
            acc[j].y = fmaf(-cy, u1[j], acc[j].y);
        }
    }
}

template <int NR>
__device__ __forceinline__ void redw(float2* acc) {
#pragma unroll
    for (int m = 1; m < 32; m <<= 1)
#pragma unroll
        for (int j = 0; j < NR; j++) {
            acc[j].x += __shfl_xor_sync(0xffffffffu, acc[j].x, m);
            acc[j].y += __shfl_xor_sync(0xffffffffu, acc[j].y, m);
        }
}

__device__ __forceinline__ void sumc(const float (*sp)[32], float* s_c, int tid, float lr) {
    if (tid < 32) {
        float s = 0.f;
#pragma unroll
        for (int rr = 0; rr < RCTA; rr++) s += sp[rr][tid];
        s_c[tid] = lr * s;
    }
    __syncthreads();
}

template <int NPC, int KD>
__device__ __forceinline__ void publish(float2* dst_vec, float* dst_part,
                                        const float2* s_new,
                                        const float* __restrict__ histA,
                                        int b0, int r, int t, int tid) {
    __syncthreads();
    if (tid < NPC) {
        float2 v = s_new[tid];
        uint32_t sa = s2u(&dst_vec[r * NPC + tid]);
#pragma unroll
        for (int rr = 0; rr < RCTA; rr++) st_cluster_f2(sa, rr, v);
    }
    int w = tid >> 5, lane = tid & 31;
    if (w < t) {
        float a0 = 0.f, a1 = 0.f;
#pragma unroll
        for (int ii = 0; ii < NPC / 32; ii++) {
            int i = lane + 32 * ii;
            float2 nv = s_new[i];
            float h0 = histA[(size_t)(b0 * TT + w) * KD + r * NPC + i];
            float h1 = histA[(size_t)((b0 + 1) * TT + w) * KD + r * NPC + i];
            a0 = fmaf(h0, nv.x, a0);
            a1 = fmaf(h1, nv.y, a1);
        }
        a0 = warp_sum(a0); a1 = warp_sum(a1);
        if (lane == 0) {
            uint32_t sa = s2u(&dst_part[r * 32 + 2 * w]);
#pragma unroll
            for (int rr = 0; rr < RCTA; rr++) st_cluster_f2(sa, rr, make_float2(a0, a1));
        }
    }
}

__global__ void __cluster_dims__(RCTA, 1, 1) __launch_bounds__(TPB, 1)
k_train(const float* __restrict__ tx, const float* __restrict__ ty,
        const float* __restrict__ tg,
        const float* __restrict__ fc1, const float* __restrict__ fc2,
        const float* __restrict__ fc3, const float* __restrict__ fc4,
        const float* __restrict__ loglr) {
    __shared__ __align__(16) float2 s_vec[2][HH];
    __shared__ __align__(16) float s_part[2][RCTA][32];
    __shared__ __align__(16) float2 s_new[64];
    __shared__ float s_c[32];
    int tid = threadIdx.x;
    int r = blockIdx.x & (RCTA - 1);
    int b0 = (blockIdx.x / RCTA) * 2;
    int w = tid >> 5, lane = tid & 31;
    int nb4 = r * 64 + w * 4;
    int nb2 = r * 32 + w * 2;
    float lr = expf(*loglr);
    float2 acc[4];

    for (int t = 0; t < TT; t++) {
        // ======== fwd1 ========
        {
            const float* x0 = tx + (size_t)(b0 * TT + t) * XX;
            const float* x1 = tx + (size_t)((b0 + 1) * TT + t) * XX;
            for (int k = tid; k < XX; k += TPB)
                s_vec[0][k] = make_float2(x0[k], x1[k]);
            if (tid < 32) {
                int s = tid >> 1, bsel = tid & 1;
                s_c[tid] = (s < t) ? lr * g_xg[((b0 + bsel) * TT + s) * TT + t] : 0.f;
            }
            __syncthreads();
            XR<XX> X;
            ldx<XX>(X, s_vec[0], lane);
#pragma unroll
            for (int j = 0; j < 4; j++) acc[j] = dotrow<XX>(fc1, nb4 + j, X, lane);
            corrw<HH, 4>(g_dz1A, b0, nb4, s_c, t, lane, acc);
            redw<4>(acc);
            if (lane < 4) {
                float2 a = (lane == 0) ? acc[0] : (lane == 1) ? acc[1]
                         : (lane == 2) ? acc[2] : acc[3];
                int n = nb4 + lane;
                float h0 = fmaxf(a.x + g_b1[b0 * HH + n], 0.f);
                float h1 = fmaxf(a.y + g_b1[(b0 + 1) * HH + n], 0.f);
                g_h1A[(size_t)(b0 * TT + t) * HH + n] = h0;
                g_h1A[(size_t)((b0 + 1) * TT + t) * HH + n] = h1;
                s_new[w * 4 + lane] = make_float2(h0, h1);
            }
            publish<64, HH>(s_vec[1], &s_part[1][0][0], s_new, g_h1A, b0, r, t, tid);
            csync();
        }
        // ======== fwd2 ========
        {
            sumc(s_part[1], s_c, tid, lr);
            XR<HH> X;
            ldx<HH>(X, s_vec[1], lane);
#pragma unroll
            for (int j = 0; j < 4; j++) acc[j] = dotrow<HH>(fc2, nb4 + j, X, lane);
            corrw<HH, 4>(g_dz2A, b0, nb4, s_c, t, lane, acc);
            redw<4>(acc);
            if (lane < 4) {
                float2 a = (lane == 0) ? acc[0] : (lane == 1) ? acc[1]
                         : (lane == 2) ? acc[2] : acc[3];
                int n = nb4 + lane;
                float h0 = fmaxf(a.x + g_b2[b0 * HH + n], 0.f);
                float h1 = fmaxf(a.y + g_b2[(b0 + 1) * HH + n], 0.f);
                g_h2A[(size_t)(b0 * TT + t) * HH + n] = h0;
                g_h2A[(size_t)((b0 + 1) * TT + t) * HH + n] = h1;
                s_new[w * 4 + lane] = make_float2(h0, h1);
            }
            publish<64, HH>(s_vec[0], &s_part[0][0][0], s_new, g_h2A, b0, r, t, tid);
            csync();
        }
        // ======== fwd3 + gate ========
        {
            sumc(s_part[0], s_c, tid, lr);
            XR<HH> X;
            ldx<HH>(X, s_vec[0], lane);
#pragma unroll
            for (int j = 0; j < 4; j++) acc[j] = dotrow<HH>(fc3, nb4 + j, X, lane);
            corrw<HH, 4>(g_dz3A, b0, nb4, s_c, t, lane, acc);
            redw<4>(acc);
            if (lane < 4) {
                float2 a = (lane == 0) ? acc[0] : (lane == 1) ? acc[1]
                         : (lane == 2) ? acc[2] : acc[3];
                int n = nb4 + lane;
                float h30 = fmaxf(a.x + g_b3[b0 * HH + n], 0.f);
                float h31 = fmaxf(a.y + g_b3[(b0 + 1) * HH + n], 0.f);
                g_h3A[(size_t)(b0 * TT + t) * HH + n] = h30;
                g_h3A[(size_t)((b0 + 1) * TT + t) * HH + n] = h31;
                float hg0 = h30 * tg[(size_t)(b0 * TT + t) * HH + n];
                float hg1 = h31 * tg[(size_t)((b0 + 1) * TT + t) * HH + n];
                g_hgA[(size_t)(b0 * TT + t) * HH + n] = hg0;
                g_hgA[(size_t)((b0 + 1) * TT + t) * HH + n] = hg1;
                s_new[w * 4 + lane] = make_float2(hg0, hg1);
            }
            publish<64, HH>(s_vec[1], &s_part[1][0][0], s_new, g_hgA, b0, r, t, tid);
            csync();
        }
        // ======== fwd4 -> dlogit ========
        {
            sumc(s_part[1], s_c, tid, lr);
            XR<HH> X;
            ldx<HH>(X, s_vec[1], lane);
#pragma unroll
            for (int j = 0; j < 2; j++) acc[j] = dotrow<HH>(fc4, nb2 + j, X, lane);
            corrw<YY, 2>(g_dlA, b0, nb2, s_c, t, lane, acc);
            redw<2>(acc);
            if (lane < 2) {
                float2 a = lane ? acc[1] : acc[0];
                int n = nb2 + lane;
                float d0 = (2.f / (float)YY) * (a.x - ty[(size_t)(b0 * TT + t) * YY + n]);
                float d1 = (2.f / (float)YY) * (a.y - ty[(size_t)((b0 + 1) * TT + t) * YY + n]);
                g_dlA[(size_t)(b0 * TT + t) * YY + n] = d0;
                g_dlA[(size_t)((b0 + 1) * TT + t) * YY + n] = d1;
                s_new[w * 2 + lane] = make_float2(d0, d1);
            }
            publish<32, YY>(s_vec[0], &s_part[0][0][0], s_new, g_dlA, b0, r, t, tid);
            csync();
        }
        // ======== bwd4 ========
        {
            sumc(s_part[0], s_c, tid, lr);
            XR<YY> X;
            ldx<YY>(X, s_vec[0], lane);
#pragma unroll
            for (int j = 0; j < 4; j++) acc[j] = dotrow<YY>(g_w4T, nb4 + j, X, lane);
            corrw<HH, 4>(g_hgA, b0, nb4, s_c, t, lane, acc);
            redw<4>(acc);
            if (lane < 4) {
                float2 a = (lane == 0) ? acc[0] : (lane == 1) ? acc[1]
                         : (lane == 2) ? acc[2] : acc[3];
                int n = nb4 + lane;
                float h30 = g_h3A[(size_t)(b0 * TT + t) * HH + n];
                float h31 = g_h3A[(size_t)((b0 + 1) * TT + t) * HH + n];
                float d0 = (h30 > 0.f) ? a.x * tg[(size_t)(b0 * TT + t) * HH + n] : 0.f;
                float d1 = (h31 > 0.f) ? a.y * tg[(size_t)((b0 + 1) * TT + t) * HH + n] : 0.f;
                g_dz3A[(size_t)(b0 * TT + t) * HH + n] = d0;
                g_dz3A[(size_t)((b0 + 1) * TT + t) * HH + n] = d1;
                g_b3[b0 * HH + n] -= lr * d0;
                g_b3[(b0 + 1) * HH + n] -= lr * d1;
                s_new[w * 4 + lane] = make_float2(d0, d1);
            }
            publish<64, HH>(s_vec[1], &s_part[1][0][0], s_new, g_dz3A, b0, r, t, tid);
            csync();
        }
        // ======== bwd3 ========
        {
            sumc(s_part[1], s_c, tid, lr);
            XR<HH> X;
            ldx<HH>(X, s_vec[1], lane);
#pragma unroll
            for (int j = 0; j < 4; j++) acc[j] = dotrow<HH>(g_w3T, nb4 + j, X, lane);
            corrw<HH, 4>(g_h2A, b0, nb4, s_c, t, lane, acc);
            redw<4>(acc);
            if (lane < 4) {
                float2 a = (lane == 0) ? acc[0] : (lane == 1) ? acc[1]
                         : (lane == 2) ? acc[2] : acc[3];
                int n = nb4 + lane;
                float h20 = g_h2A[(size_t)(b0 * TT + t) * HH + n];
                float h21 = g_h2A[(size_t)((b0 + 1) * TT + t) * HH + n];
                float d0 = (h20 > 0.f) ? a.x : 0.f;
                float d1 = (h21 > 0.f) ? a.y : 0.f;
                g_dz2A[(size_t)(b0 * TT + t) * HH + n] = d0;
                g_dz2A[(size_t)((b0 + 1) * TT + t) * HH + n] = d1;
                g_b2[b0 * HH + n] -= lr * d0;
                g_b2[(b0 + 1) * HH + n] -= lr * d1;
                s_new[w * 4 + lane] = make_float2(d0, d1);
            }
            publish<64, HH>(s_vec[0], &s_part[0][0][0], s_new, g_dz2A, b0, r, t, tid);
            csync();
        }
        // ======== bwd2 ========
        {
            sumc(s_part[0], s_c, tid, lr);
            XR<HH> X;
            ldx<HH>(X, s_vec[0], lane);
#pragma unroll
            for (int j = 0; j < 4; j++) acc[j] = dotrow<HH>(g_w2T, nb4 + j, X, lane);
            corrw<HH, 4>(g_h1A, b0, nb4, s_c, t, lane, acc);
            redw<4>(acc);
            if (lane < 4) {
                float2 a = (lane == 0) ? acc[0] : (lane == 1) ? acc[1]
                         : (lane == 2) ? acc[2] : acc[3];
                int n = nb4 + lane;
                float h10 = g_h1A[(size_t)(b0 * TT + t) * HH + n];
                float h11 = g_h1A[(size_t)((b0 + 1) * TT + t) * HH + n];
                float d0 = (h10 > 0.f) ? a.x : 0.f;
                float d1 = (h11 > 0.f) ? a.y : 0.f;
                g_dz1A[(size_t)(b0 * TT + t) * HH + n] = d0;
                g_dz1A[(size_t)((b0 + 1) * TT + t) * HH + n] = d1;
                g_b1[b0 * HH + n] -= lr * d0;
                g_b1[(b0 + 1) * HH + n] -= lr * d1;
            }
            __syncthreads();
        }
    }
}

// ---------------- cf: Cf[b][s][l] = lr * (V[b][s] . X[b][l]) -----------------
template <int LAYER>
__global__ void __launch_bounds__(256) k_cf(const float* __restrict__ vext,
                                            const float* __restrict__ extin,
                                            const float* __restrict__ loglr) {
    constexpr int K = (LAYER == 1) ? XX : HH;
    __shared__ float Xs[64 * 33];
    __shared__ float Vs[16 * 33];
    int b = blockIdx.x >> 1, lh = blockIdx.x & 1;
    const float* V = (LAYER == 1) ? vext : (LAYER == 2) ? g_h1A
                   : (LAYER == 3) ? g_h2A : g_hgA;
    const float* in = (LAYER == 1) ? extin : (LAYER == 2) ? g_ea
                    : (LAYER == 3) ? g_eb : g_ea;
    const float* Vb = V + (size_t)(b * TT) * K;
    const float* Ib = in + ((size_t)b * LL + lh * 64) * K;
    int tid = threadIdx.x;
    int l = tid & 63, sg = tid >> 6;
    float acc[4] = {0.f, 0.f, 0.f, 0.f};
    float lr = expf(*loglr);
    for (int kc = 0; kc < K; kc += 32) {
#pragma unroll
        for (int s8 = 0; s8 < 8; s8++) {
            int e = tid + s8 * 256;
            int kk = e & 31, ll = e >> 5;
            Xs[ll * 33 + kk] = Ib[(size_t)ll * K + kc + kk];
        }
#pragma unroll
        for (int q = 0; q < 2; q++) {
            int e = tid + q * 256;
            int kk = e & 31, ss = e >> 5;
            Vs[ss * 33 + kk] = Vb[(size_t)ss * K + kc + kk];
        }
        __syncthreads();
#pragma unroll
        for (int kk = 0; kk < 32; kk++) {
            float xv = Xs[l * 33 + kk];
#pragma unroll
            for (int j = 0; j < 4; j++)
                acc[j] = fmaf(Vs[(sg * 4 + j) * 33 + kk], xv, acc[j]);
        }
        __syncthreads();
    }
#pragma unroll
    for (int j = 0; j < 4; j++)
        g_cf[(size_t)(b * TT + sg * 4 + j) * LL + lh * 64 + l] = lr * acc[j];
}

// ---------------- eval: fused low-rank GEMM, true FFMA2 ----------------------
// Ws2 duplicated layout: Ws2[kk*258 + 2n] = Ws2[kk*258 + 2n + 1] = W[n][kk]
// Xs kk-major, stride 66 (even -> aligned 64-bit pairs over l)
template <int LAYER>
__global__ void __launch_bounds__(256) k_eval(const float* __restrict__ extin,
                                              const float* __restrict__ gate,
                                              float* __restrict__ outp,
                                              const float* __restrict__ W0) {
    constexpr int N = (LAYER == 4) ? YY : HH;
    constexpr int K = (LAYER == 1) ? XX : HH;
    constexpr int NBLK = N / 128;
    __shared__ __align__(16) float Ws2[32 * 258];
    __shared__ __align__(16) float Xs[32 * 66];
    __shared__ float Cs[TT][65];
    int lb = blockIdx.x & 1;
    int tmp = blockIdx.x >> 1;
    int nb = tmp & (NBLK - 1);
    int b = tmp / NBLK;
    const float* in = (LAYER == 1) ? extin : (LAYER == 2) ? g_ea : (LAYER == 3) ? g_eb : g_ea;
    const float* U = (LAYER == 1) ? g_dz1A : (LAYER == 2) ? g_dz2A
                   : (LAYER == 3) ? g_dz3A : g_dlA;
    const float* Wb = W0 + (size_t)(nb * 128) * K;
    const float* Ib = in + ((size_t)b * LL + lb * 64) * K;
    int tid = threadIdx.x;
    int tc = tid & 31, tr = tid >> 5;

#pragma unroll
    for (int q = 0; q < 4; q++) {
        int e = tid + q * 256;
        int s = e >> 6, l = e & 63;
        Cs[s][l] = g_cf[(size_t)(b * TT + s) * LL + lb * 64 + l];
    }

    unsigned long long acc[4][4];   // [l-pair ip][n-col d]
#pragma unroll
    for (int i = 0; i < 4; i++)
#pragma unroll
        for (int d = 0; d < 4; d++) acc[i][d] = 0ull;

    for (int kc = 0; kc < K; kc += 32) {
#pragma unroll
        for (int s = 0; s < 16; s++) {
            int e = tid + s * 256;
            int kk = e & 31, n = e >> 5;
            float wv = Wb[(size_t)n * K + kc + kk];
            *(float2*)&Ws2[kk * 258 + 2 * n] = make_float2(wv, wv);
        }
#pragma unroll
        for (int s = 0; s < 8; s++) {
            int e = tid + s * 256;
            int kk = e & 31, l = e >> 5;
            Xs[kk * 66 + l] = Ib[(size_t)l * K + kc + kk];
        }
        __syncthreads();
#pragma unroll
        for (int kk = 0; kk < 32; kk++) {
            unsigned long long w0 = *(const unsigned long long*)&Ws2[kk * 258 + 2 * tc];
            unsigned long long w1 = *(const unsigned long long*)&Ws2[kk * 258 + 64 + 2 * tc];
            unsigned long long w2 = *(const unsigned long long*)&Ws2[kk * 258 + 128 + 2 * tc];
            unsigned long long w3 = *(const unsigned long long*)&Ws2[kk * 258 + 192 + 2 * tc];
#pragma unroll
            for (int ip = 0; ip < 4; ip++) {
                unsigned long long xp =
                    *(const unsigned long long*)&Xs[kk * 66 + tr * 8 + 2 * ip];
                ffma2l(acc[ip][0], xp, w0);
                ffma2l(acc[ip][1], xp, w1);
                ffma2l(acc[ip][2], xp, w2);
                ffma2l(acc[ip][3], xp, w3);
            }
        }
        __syncthreads();
    }

    float bv[4] = {0.f, 0.f, 0.f, 0.f};
    if (LAYER != 4) {
        const float* bias = (LAYER == 1) ? g_b1 : (LAYER == 2) ? g_b2 : g_b3;
#pragma unroll
        for (int d = 0; d < 4; d++) bv[d] = bias[b * HH + nb * 128 + tc + 32 * d];
    }
    float* op = (LAYER == 4) ? outp : (LAYER == 1) ? g_ea : (LAYER == 2) ? g_eb : g_ea;

#pragma unroll
    for (int ip = 0; ip < 4; ip++) {
        float us;  // per-s U value loaded inside correction loop
        float2 pr[4];
#pragma unroll
        for (int d = 0; d < 4; d++) pr[d] = unpk(acc[ip][d]);
        // rank-16 correction on unpacked scalars
#pragma unroll
        for (int s = 0; s < TT; s++) {
            float cf0 = Cs[s][tr * 8 + 2 * ip];
            float cf1 = Cs[s][tr * 8 + 2 * ip + 1];
#pragma unroll
            for (int d = 0; d < 4; d++) {
                us = U[(size_t)(b * TT + s) * N + nb * 128 + tc + 32 * d];
                pr[d].x = fmaf(-cf0, us, pr[d].x);
                pr[d].y = fmaf(-cf1, us, pr[d].y);
            }
        }
#pragma unroll
        for (int h = 0; h < 2; h++) {
            int l = lb * 64 + tr * 8 + 2 * ip + h;
            size_t rowo = ((size_t)b * LL + l) * N + nb * 128;
#pragma unroll
            for (int d = 0; d < 4; d++) {
                float v = h ? pr[d].y : pr[d].x;
                if (LAYER != 4) v = fmaxf(v + bv[d], 0.f);
                if (LAYER == 3)
                    v *= gate[((size_t)b * LL + l) * HH + nb * 128 + tc + 32 * d];
                op[rowo + tc + 32 * d] = v;
            }
        }
    }
}

__global__ void k_loss(const float* __restrict__ ty, const float* __restrict__ loglr,
                       float* __restrict__ out) {
    int gw = (blockIdx.x * blockDim.x + threadIdx.x) >> 5;
    int lane = threadIdx.x & 31;
    if (gw >= BB * LL) return;
    const float* lg = out + 4097 + (size_t)gw * YY;
    const float* tyv = ty + (size_t)gw * YY;
    float acc = 0.f;
#pragma unroll
    for (int k = lane, it = 0; it < YY / 32; it++, k += 32) {
        float d = lg[k] - tyv[k];
        acc = fmaf(d, d, acc);
    }
    acc = warp_sum(acc);
    if (lane == 0) {
        float m = acc * (1.f / (float)YY);
        out[gw] = m;
        out[2049 + gw] = m;
    }
    if (gw == 0 && lane == 0) out[2048] = expf(*loglr);
}

extern "C" void kernel_launch(void* const* d_in, const int* in_sizes, int n_in,
                              void* d_out, int out_size) {
    const float* train_x = (const float*)d_in[0];
    const float* train_y = (const float*)d_in[1];
    const float* test_x = (const float*)d_in[2];
    const float* test_y = (const float*)d_in[3];
    const float* train_gate = (const float*)d_in[4];
    const float* test_gate = (const float*)d_in[5];
    const float* fc1 = (const float*)d_in[6];
    const float* b1 = (const float*)d_in[7];
    const float* fc2 = (const float*)d_in[8];
    const float* b2 = (const float*)d_in[9];
    const float* fc3 = (const float*)d_in[10];
    const float* b3 = (const float*)d_in[11];
    const float* fc4 = (const float*)d_in[12];
    const float* loglr = (const float*)d_in[13];
    float* out = (float*)d_out;

    k_tr<<<640, 256>>>(fc2, fc3, fc4);
    k_miscA<<<32, 256>>>(b1, b2, b3);
    k_miscB<<<64, 256>>>(train_x);
    k_train<<<64, TPB>>>(train_x, train_y, train_gate, fc1, fc2, fc3, fc4, loglr);

    k_cf<1><<<32, 256>>>(train_x, test_x, loglr);
    k_eval<1><<<BB * (HH / 128) * 2, 256>>>(test_x, nullptr, nullptr, fc1);
    k_cf<2><<<32, 256>>>(nullptr, nullptr, loglr);
    k_eval<2><<<BB * (HH / 128) * 2, 256>>>(nullptr, nullptr, nullptr, fc2);
    k_cf<3><<<32, 256>>>(nullptr, nullptr, loglr);
    k_eval<3><<<BB * (HH / 128) * 2, 256>>>(nullptr, test_gate, nullptr, fc3);
    k_cf<4><<<32, 256>>>(nullptr, nullptr, loglr);
    k_eval<4><<<BB * (YY / 128) * 2, 256>>>(nullptr, nullptr, out + 4097, fc4);

    k_loss<<<256, 256>>>(test_y, loglr, out);
}

// round 15
// speedup vs baseline: 1.5254x; 1.5254x over previous
#include <cuda_runtime.h>
#include <math.h>
#include <stdint.h>

#define BB 16
#define TT 16
#define LL 128
#define XX 256
#define HH 512
#define YY 256
#define RCTA 8
#define TPB 512

__device__ __align__(16) float g_b1[BB * HH];
__device__ __align__(16) float g_b2[BB * HH];
__device__ __align__(16) float g_b3[BB * HH];
__device__ __align__(16) float g_w2T[HH * HH];
__device__ __align__(16) float g_w3T[HH * HH];
__device__ __align__(16) float g_w4T[HH * YY];
__device__ __align__(16) float g_h1A[BB * TT * HH];
__device__ __align__(16) float g_h2A[BB * TT * HH];
__device__ __align__(16) float g_h3A[BB * TT * HH];
__device__ __align__(16) float g_hgA[BB * TT * HH];
__device__ __align__(16) float g_dz1A[BB * TT * HH];
__device__ __align__(16) float g_dz2A[BB * TT * HH];
__device__ __align__(16) float g_dz3A[BB * TT * HH];
__device__ __align__(16) float g_dlA[BB * TT * YY];
__device__ __align__(16) float g_xg[BB * TT * TT];
__device__ __align__(16) float g_ea[BB * LL * HH];
__device__ __align__(16) float g_eb[BB * LL * HH];
__device__ __align__(16) float g_cf[BB * TT * LL];

__device__ __forceinline__ float warp_sum(float v) {
    v += __shfl_xor_sync(0xffffffffu, v, 16);
    v += __shfl_xor_sync(0xffffffffu, v, 8);
    v += __shfl_xor_sync(0xffffffffu, v, 4);
    v += __shfl_xor_sync(0xffffffffu, v, 2);
    v += __shfl_xor_sync(0xffffffffu, v, 1);
    return v;
}

__device__ __forceinline__ void csync() {
    asm volatile("barrier.cluster.arrive.aligned;" ::: "memory");
    asm volatile("barrier.cluster.wait.aligned;" ::: "memory");
}

__device__ __forceinline__ uint32_t s2u(const void* p) {
    return (uint32_t)__cvta_generic_to_shared(p);
}

__device__ __forceinline__ void st_cluster_f2(uint32_t saddr, int rank, float2 v) {
    uint32_t ra;
    unsigned long long u =
        ((unsigned long long)__float_as_uint(v.y) << 32) | __float_as_uint(v.x);
    asm volatile("mapa.shared::cluster.u32 %0, %1, %2;" : "=r"(ra) : "r"(saddr), "r"(rank));
    asm volatile("st.shared::cluster.b64 [%0], %1;" :: "r"(ra), "l"(u) : "memory");
}

// ---------------- pre-passes ----------------
__global__ void __launch_bounds__(256) k_tr(const float* __restrict__ fc2,
                                            const float* __restrict__ fc3,
                                            const float* __restrict__ fc4) {
    __shared__ float tile[32][33];
    int bid = blockIdx.x;
    const float* src;
    float* dst;
    int RS, CS;
    if (bid < 256) { src = fc2; dst = g_w2T; RS = HH; CS = HH; }
    else if (bid < 512) { src = fc3; dst = g_w3T; bid -= 256; RS = HH; CS = HH; }
    else { src = fc4; dst = g_w4T; bid -= 512; RS = YY; CS = HH; }
    int tpr = CS / 32;
    int r0 = (bid / tpr) * 32, c0 = (bid % tpr) * 32;
    int tx = threadIdx.x & 31, ty = threadIdx.x >> 5;
    for (int i = ty; i < 32; i += 8) tile[i][tx] = src[(size_t)(r0 + i) * CS + c0 + tx];
    __syncthreads();
    for (int i = ty; i < 32; i += 8) dst[(size_t)(c0 + i) * RS + r0 + tx] = tile[tx][i];
}

__global__ void __launch_bounds__(256) k_miscA(const float* __restrict__ b1,
                                               const float* __restrict__ b2,
                                               const float* __restrict__ b3) {
    int gt = blockIdx.x * blockDim.x + threadIdx.x;
    int NT = gridDim.x * blockDim.x;
    for (int i = gt; i < BB * HH; i += NT) {
        int k = i & (HH - 1);
        g_b1[i] = b1[k]; g_b2[i] = b2[k]; g_b3[i] = b3[k];
    }
}

__global__ void __launch_bounds__(256) k_miscB(const float* __restrict__ tx) {
    int gt = blockIdx.x * blockDim.x + threadIdx.x;
    int NT = gridDim.x * blockDim.x;
    int gw = gt >> 5, lane = gt & 31;
    for (int d = gw; d < BB * TT * TT; d += NT >> 5) {
        int b = d >> 8, s1 = (d >> 4) & 15, s2 = d & 15;
        const float4* xa = (const float4*)(tx + (size_t)(b * TT + s1) * XX);
        const float4* xb = (const float4*)(tx + (size_t)(b * TT + s2) * XX);
        float4 a = xa[lane], c = xb[lane];
        float acc = a.x * c.x + a.y * c.y + a.z * c.z + a.w * c.w;
        a = xa[lane + 32]; c = xb[lane + 32];
        acc += a.x * c.x + a.y * c.y + a.z * c.z + a.w * c.w;
        acc = warp_sum(acc);
        if (lane == 0) g_xg[d] = acc;
    }
}

// ---------------- train compute core: warp-tiled rows, x in regs -------------
template <int K>
struct XR { float4 a[K / 128][2]; };

template <int K>
__device__ __forceinline__ void ldx(XR<K>& X, const float2* sv, int lane) {
#pragma unroll
    for (int i = 0; i < K / 128; i++) {
        const float4* p = (const float4*)(sv + 4 * lane + 128 * i);
        X.a[i][0] = p[0];
        X.a[i][1] = p[1];
    }
}

template <int K>
__device__ __forceinline__ float2 dotrow(const float* __restrict__ W, int n,
                                         const XR<K>& X, int lane) {
    float a0 = 0.f, a1 = 0.f, b0v = 0.f, b1v = 0.f;
#pragma unroll
    for (int i = 0; i < K / 128; i++) {
        float4 w = *(const float4*)(W + (size_t)n * K + 4 * lane + 128 * i);
        a0 = fmaf(w.x, X.a[i][0].x, a0); a1 = fmaf(w.x, X.a[i][0].y, a1);
        b0v = fmaf(w.y, X.a[i][0].z, b0v); b1v = fmaf(w.y, X.a[i][0].w, b1v);
        a0 = fmaf(w.z, X.a[i][1].x, a0); a1 = fmaf(w.z, X.a[i][1].y, a1);
        b0v = fmaf(w.w, X.a[i][1].z, b0v); b1v = fmaf(w.w, X.a[i][1].w, b1v);
    }
    return make_float2(a0 + b0v, a1 + b1v);
}

// lane s (<t) applies correction term s to all rows' partials (pre-reduce)
template <int NU, int NR>
__device__ __forceinline__ void corrw(const float* __restrict__ uA, int b0, int nb,
                                      const float* s_c, int t, int lane, float2* acc) {
    if (lane < t) {
        float cx = s_c[2 * lane], cy = s_c[2 * lane + 1];
        const float* u0 = uA + (size_t)(b0 * TT + lane) * NU + nb;
        const float* u1 = uA + (size_t)((b0 + 1) * TT + lane) * NU + nb;
#pragma unroll
        for (int j = 0; j < NR; j++) {
            acc[j].x = fmaf(-cx, u0[j], acc[j].x);
            acc[j].y = fmaf(-cy, u1[j], acc[j].y);
        }
    }
}

template <int NR>
__device__ __forceinline__ void redw(float2* acc) {
#pragma unroll
    for (int m = 1; m < 32; m <<= 1)
#pragma unroll
        for (int j = 0; j < NR; j++) {
            acc[j].x += __shfl_xor_sync(0xffffffffu, acc[j].x, m);
            acc[j].y += __shfl_xor_sync(0xffffffffu, acc[j].y, m);
        }
}

__device__ __forceinline__ void sumc(const float (*sp)[32], float* s_c, int tid, float lr) {
    if (tid < 32) {
        float s = 0.f;
#pragma unroll
        for (int rr = 0; rr < RCTA; rr++) s += sp[rr][tid];
        s_c[tid] = lr * s;
    }
    __syncthreads();
}

template <int NPC, int KD>
__device__ __forceinline__ void publish(float2* dst_vec, float* dst_part,
                                        const float2* s_new,
                                        const float* __restrict__ histA,
                                        int b0, int r, int t, int tid) {
    __syncthreads();
    if (tid < NPC) {
        float2 v = s_new[tid];
        uint32_t sa = s2u(&dst_vec[r * NPC + tid]);
#pragma unroll
        for (int rr = 0; rr < RCTA; rr++) st_cluster_f2(sa, rr, v);
    }
    int w = tid >> 5, lane = tid & 31;
    if (w < t) {
        float a0 = 0.f, a1 = 0.f;
#pragma unroll
        for (int ii = 0; ii < NPC / 32; ii++) {
            int i = lane + 32 * ii;
            float2 nv = s_new[i];
            float h0 = histA[(size_t)(b0 * TT + w) * KD + r * NPC + i];
            float h1 = histA[(size_t)((b0 + 1) * TT + w) * KD + r * NPC + i];
            a0 = fmaf(h0, nv.x, a0);
            a1 = fmaf(h1, nv.y, a1);
        }
        a0 = warp_sum(a0); a1 = warp_sum(a1);
        if (lane == 0) {
            uint32_t sa = s2u(&dst_part[r * 32 + 2 * w]);
#pragma unroll
            for (int rr = 0; rr < RCTA; rr++) st_cluster_f2(sa, rr, make_float2(a0, a1));
        }
    }
}

__global__ void __cluster_dims__(RCTA, 1, 1) __launch_bounds__(TPB, 1)
k_train(const float* __restrict__ tx, const float* __restrict__ ty,
        const float* __restrict__ tg,
        const float* __restrict__ fc1, const float* __restrict__ fc2,
        const float* __restrict__ fc3, const float* __restrict__ fc4,
        const float* __restrict__ loglr) {
    __shared__ __align__(16) float2 s_vec[2][HH];
    __shared__ __align__(16) float s_part[2][RCTA][32];
    __shared__ __align__(16) float2 s_new[64];
    __shared__ float s_c[32];
    int tid = threadIdx.x;
    int r = blockIdx.x & (RCTA - 1);
    int b0 = (blockIdx.x / RCTA) * 2;
    int w = tid >> 5, lane = tid & 31;
    int nb4 = r * 64 + w * 4;   // 4 rows/warp for HH-output phases
    int nb2 = r * 32 + w * 2;   // 2 rows/warp for fwd4 (YY output)
    float lr = expf(*loglr);
    float2 acc[4];

    for (int t = 0; t < TT; t++) {
        // ======== fwd1: K=XX, W=fc1 -> h1 (buf0 local, pub -> buf1) ========
        {
            const float* x0 = tx + (size_t)(b0 * TT + t) * XX;
            const float* x1 = tx + (size_t)((b0 + 1) * TT + t) * XX;
            for (int k = tid; k < XX; k += TPB)
                s_vec[0][k] = make_float2(x0[k], x1[k]);
            if (tid < 32) {
                int s = tid >> 1, bsel = tid & 1;
                s_c[tid] = (s < t) ? lr * g_xg[((b0 + bsel) * TT + s) * TT + t] : 0.f;
            }
            __syncthreads();
            XR<XX> X;
            ldx<XX>(X, s_vec[0], lane);
#pragma unroll
            for (int j = 0; j < 4; j++) acc[j] = dotrow<XX>(fc1, nb4 + j, X, lane);
            corrw<HH, 4>(g_dz1A, b0, nb4, s_c, t, lane, acc);
            redw<4>(acc);
            if (lane < 4) {
                float2 a = (lane == 0) ? acc[0] : (lane == 1) ? acc[1]
                         : (lane == 2) ? acc[2] : acc[3];
                int n = nb4 + lane;
                float h0 = fmaxf(a.x + g_b1[b0 * HH + n], 0.f);
                float h1 = fmaxf(a.y + g_b1[(b0 + 1) * HH + n], 0.f);
                g_h1A[(size_t)(b0 * TT + t) * HH + n] = h0;
                g_h1A[(size_t)((b0 + 1) * TT + t) * HH + n] = h1;
                s_new[w * 4 + lane] = make_float2(h0, h1);
            }
            publish<64, HH>(s_vec[1], &s_part[1][0][0], s_new, g_h1A, b0, r, t, tid);
            csync();
        }
        // ======== fwd2: K=HH, W=fc2 (buf1 -> buf0) ========
        {
            sumc(s_part[1], s_c, tid, lr);
            XR<HH> X;
            ldx<HH>(X, s_vec[1], lane);
#pragma unroll
            for (int j = 0; j < 4; j++) acc[j] = dotrow<HH>(fc2, nb4 + j, X, lane);
            corrw<HH, 4>(g_dz2A, b0, nb4, s_c, t, lane, acc);
            redw<4>(acc);
            if (lane < 4) {
                float2 a = (lane == 0) ? acc[0] : (lane == 1) ? acc[1]
                         : (lane == 2) ? acc[2] : acc[3];
                int n = nb4 + lane;
                float h0 = fmaxf(a.x + g_b2[b0 * HH + n], 0.f);
                float h1 = fmaxf(a.y + g_b2[(b0 + 1) * HH + n], 0.f);
                g_h2A[(size_t)(b0 * TT + t) * HH + n] = h0;
                g_h2A[(size_t)((b0 + 1) * TT + t) * HH + n] = h1;
                s_new[w * 4 + lane] = make_float2(h0, h1);
            }
            publish<64, HH>(s_vec[0], &s_part[0][0][0], s_new, g_h2A, b0, r, t, tid);
            csync();
        }
        // ======== fwd3 + gate: K=HH, W=fc3 (buf0 -> buf1) ========
        {
            sumc(s_part[0], s_c, tid, lr);
            XR<HH> X;
            ldx<HH>(X, s_vec[0], lane);
#pragma unroll
            for (int j = 0; j < 4; j++) acc[j] = dotrow<HH>(fc3, nb4 + j, X, lane);
            corrw<HH, 4>(g_dz3A, b0, nb4, s_c, t, lane, acc);
            redw<4>(acc);
            if (lane < 4) {
                float2 a = (lane == 0) ? acc[0] : (lane == 1) ? acc[1]
                         : (lane == 2) ? acc[2] : acc[3];
                int n = nb4 + lane;
                float h30 = fmaxf(a.x + g_b3[b0 * HH + n], 0.f);
                float h31 = fmaxf(a.y + g_b3[(b0 + 1) * HH + n], 0.f);
                g_h3A[(size_t)(b0 * TT + t) * HH + n] = h30;
                g_h3A[(size_t)((b0 + 1) * TT + t) * HH + n] = h31;
                float hg0 = h30 * tg[(size_t)(b0 * TT + t) * HH + n];
                float hg1 = h31 * tg[(size_t)((b0 + 1) * TT + t) * HH + n];
                g_hgA[(size_t)(b0 * TT + t) * HH + n] = hg0;
                g_hgA[(size_t)((b0 + 1) * TT + t) * HH + n] = hg1;
                s_new[w * 4 + lane] = make_float2(hg0, hg1);
            }
            publish<64, HH>(s_vec[1], &s_part[1][0][0], s_new, g_hgA, b0, r, t, tid);
            csync();
        }
        // ======== fwd4 -> dlogit: K=HH, W=fc4 (buf1 -> buf0), 2 rows/warp ====
        {
            sumc(s_part[1], s_c, tid, lr);
            XR<HH> X;
            ldx<HH>(X, s_vec[1], lane);
#pragma unroll
            for (int j = 0; j < 2; j++) acc[j] = dotrow<HH>(fc4, nb2 + j, X, lane);
            corrw<YY, 2>(g_dlA, b0, nb2, s_c, t, lane, acc);
            redw<2>(acc);
            if (lane < 2) {
                float2 a = lane ? acc[1] : acc[0];
                int n = nb2 + lane;
                float d0 = (2.f / (float)YY) * (a.x - ty[(size_t)(b0 * TT + t) * YY + n]);
                float d1 = (2.f / (float)YY) * (a.y - ty[(size_t)((b0 + 1) * TT + t) * YY + n]);
                g_dlA[(size_t)(b0 * TT + t) * YY + n] = d0;
                g_dlA[(size_t)((b0 + 1) * TT + t) * YY + n] = d1;
                s_new[w * 2 + lane] = make_float2(d0, d1);
            }
            publish<32, YY>(s_vec[0], &s_part[0][0][0], s_new, g_dlA, b0, r, t, tid);
            csync();
        }
        // ======== bwd4: K=YY, W=w4T -> dz3, b3 (buf0 -> buf1) ========
        {
            sumc(s_part[0], s_c, tid, lr);
            XR<YY> X;
            ldx<YY>(X, s_vec[0], lane);
#pragma unroll
            for (int j = 0; j < 4; j++) acc[j] = dotrow<YY>(g_w4T, nb4 + j, X, lane);
            corrw<HH, 4>(g_hgA, b0, nb4, s_c, t, lane, acc);
            redw<4>(acc);
            if (lane < 4) {
                float2 a = (lane == 0) ? acc[0] : (lane == 1) ? acc[1]
                         : (lane == 2) ? acc[2] : acc[3];
                int n = nb4 + lane;
                float h30 = g_h3A[(size_t)(b0 * TT + t) * HH + n];
                float h31 = g_h3A[(size_t)((b0 + 1) * TT + t) * HH + n];
                float d0 = (h30 > 0.f) ? a.x * tg[(size_t)(b0 * TT + t) * HH + n] : 0.f;
                float d1 = (h31 > 0.f) ? a.y * tg[(size_t)((b0 + 1) * TT + t) * HH + n] : 0.f;
                g_dz3A[(size_t)(b0 * TT + t) * HH + n] = d0;
                g_dz3A[(size_t)((b0 + 1) * TT + t) * HH + n] = d1;
                g_b3[b0 * HH + n] -= lr * d0;
                g_b3[(b0 + 1) * HH + n] -= lr * d1;
                s_new[w * 4 + lane] = make_float2(d0, d1);
            }
            publish<64, HH>(s_vec[1], &s_part[1][0][0], s_new, g_dz3A, b0, r, t, tid);
            csync();
        }
        // ======== bwd3: K=HH, W=w3T -> dz2, b2 (buf1 -> buf0) ========
        {
            sumc(s_part[1], s_c, tid, lr);
            XR<HH> X;
            ldx<HH>(X, s_vec[1], lane);
#pragma unroll
            for (int j = 0; j < 4; j++) acc[j] = dotrow<HH>(g_w3T, nb4 + j, X, lane);
            corrw<HH, 4>(g_h2A, b0, nb4, s_c, t, lane, acc);
            redw<4>(acc);
            if (lane < 4) {
                float2 a = (lane == 0) ? acc[0] : (lane == 1) ? acc[1]
                         : (lane == 2) ? acc[2] : acc[3];
                int n = nb4 + lane;
                float h20 = g_h2A[(size_t)(b0 * TT + t) * HH + n];
                float h21 = g_h2A[(size_t)((b0 + 1) * TT + t) * HH + n];
                float d0 = (h20 > 0.f) ? a.x : 0.f;
                float d1 = (h21 > 0.f) ? a.y : 0.f;
                g_dz2A[(size_t)(b0 * TT + t) * HH + n] = d0;
                g_dz2A[(size_t)((b0 + 1) * TT + t) * HH + n] = d1;
                g_b2[b0 * HH + n] -= lr * d0;
                g_b2[(b0 + 1) * HH + n] -= lr * d1;
                s_new[w * 4 + lane] = make_float2(d0, d1);
            }
            publish<64, HH>(s_vec[0], &s_part[0][0][0], s_new, g_dz2A, b0, r, t, tid);
            csync();
        }
        // ======== bwd2: K=HH, W=w2T -> dz1, b1 (buf0; no publish) ========
        {
            sumc(s_part[0], s_c, tid, lr);
            XR<HH> X;
            ldx<HH>(X, s_vec[0], lane);
#pragma unroll
            for (int j = 0; j < 4; j++) acc[j] = dotrow<HH>(g_w2T, nb4 + j, X, lane);
            corrw<HH, 4>(g_h1A, b0, nb4, s_c, t, lane, acc);
            redw<4>(acc);
            if (lane < 4) {
                float2 a = (lane == 0) ? acc[0] : (lane == 1) ? acc[1]
                         : (lane == 2) ? acc[2] : acc[3];
                int n = nb4 + lane;
                float h10 = g_h1A[(size_t)(b0 * TT + t) * HH + n];
                float h11 = g_h1A[(size_t)((b0 + 1) * TT + t) * HH + n];
                float d0 = (h10 > 0.f) ? a.x : 0.f;
                float d1 = (h11 > 0.f) ? a.y : 0.f;
                g_dz1A[(size_t)(b0 * TT + t) * HH + n] = d0;
                g_dz1A[(size_t)((b0 + 1) * TT + t) * HH + n] = d1;
                g_b1[b0 * HH + n] -= lr * d0;
                g_b1[(b0 + 1) * HH + n] -= lr * d1;
            }
            __syncthreads();  // protect buf0 / s_c before fwd1(t+1)
        }
    }
}

// ---------------- cf: Cf[b][s][l] = lr * (V[b][s] . X[b][l]) -----------------
template <int LAYER>
__global__ void __launch_bounds__(256) k_cf(const float* __restrict__ vext,
                                            const float* __restrict__ extin,
                                            const float* __restrict__ loglr) {
    constexpr int K = (LAYER == 1) ? XX : HH;
    __shared__ float Xs[64 * 33];
    __shared__ float Vs[16 * 33];
    int b = blockIdx.x >> 1, lh = blockIdx.x & 1;
    const float* V = (LAYER == 1) ? vext : (LAYER == 2) ? g_h1A
                   : (LAYER == 3) ? g_h2A : g_hgA;
    const float* in = (LAYER == 1) ? extin : (LAYER == 2) ? g_ea
                    : (LAYER == 3) ? g_eb : g_ea;
    const float* Vb = V + (size_t)(b * TT) * K;
    const float* Ib = in + ((size_t)b * LL + lh * 64) * K;
    int tid = threadIdx.x;
    int l = tid & 63, sg = tid >> 6;
    float acc[4] = {0.f, 0.f, 0.f, 0.f};
    float lr = expf(*loglr);
    for (int kc = 0; kc < K; kc += 32) {
#pragma unroll
        for (int s8 = 0; s8 < 8; s8++) {
            int e = tid + s8 * 256;
            int kk = e & 31, ll = e >> 5;
            Xs[ll * 33 + kk] = Ib[(size_t)ll * K + kc + kk];
        }
#pragma unroll
        for (int q = 0; q < 2; q++) {
            int e = tid + q * 256;
            int kk = e & 31, ss = e >> 5;
            Vs[ss * 33 + kk] = Vb[(size_t)ss * K + kc + kk];
        }
        __syncthreads();
#pragma unroll
        for (int kk = 0; kk < 32; kk++) {
            float xv = Xs[l * 33 + kk];
#pragma unroll
            for (int j = 0; j < 4; j++)
                acc[j] = fmaf(Vs[(sg * 4 + j) * 33 + kk], xv, acc[j]);
        }
        __syncthreads();
    }
#pragma unroll
    for (int j = 0; j < 4; j++)
        g_cf[(size_t)(b * TT + sg * 4 + j) * LL + lh * 64 + l] = lr * acc[j];
}

// ---------------- eval: fused low-rank GEMM, Cf precomputed -------------------
template <int LAYER>
__global__ void __launch_bounds__(256) k_eval(const float* __restrict__ extin,
                                              const float* __restrict__ gate,
                                              float* __restrict__ outp,
                                              const float* __restrict__ W0) {
    constexpr int N = (LAYER == 4) ? YY : HH;
    constexpr int K = (LAYER == 1) ? XX : HH;
    constexpr int NBLK = N / 128;
    __shared__ float Ws[32 * 129];
    __shared__ float Xs[64 * 33];
    __shared__ float Cs[TT][65];
    int lb = blockIdx.x & 1;
    int tmp = blockIdx.x >> 1;
    int nb = tmp & (NBLK - 1);
    int b = tmp / NBLK;
    const float* in = (LAYER == 1) ? extin : (LAYER == 2) ? g_ea : (LAYER == 3) ? g_eb : g_ea;
    const float* U = (LAYER == 1) ? g_dz1A : (LAYER == 2) ? g_dz2A
                   : (LAYER == 3) ? g_dz3A : g_dlA;
    const float* Wb = W0 + (size_t)(nb * 128) * K;
    const float* Ib = in + ((size_t)b * LL + lb * 64) * K;
    int tid = threadIdx.x;
    int tc = tid & 31, tr = tid >> 5;

#pragma unroll
    for (int q = 0; q < 4; q++) {
        int e = tid + q * 256;
        int s = e >> 6, l = e & 63;
        Cs[s][l] = g_cf[(size_t)(b * TT + s) * LL + lb * 64 + l];
    }

    float acc[8][4];
#pragma unroll
    for (int i = 0; i < 8; i++)
#pragma unroll
        for (int d = 0; d < 4; d++) acc[i][d] = 0.f;
    for (int kc = 0; kc < K; kc += 32) {
#pragma unroll
        for (int s = 0; s < 16; s++) {
            int e = tid + s * 256;
            int kk = e & 31, n = e >> 5;
            Ws[kk * 129 + n] = Wb[(size_t)n * K + kc + kk];
        }
#pragma unroll
        for (int s = 0; s < 8; s++) {
            int e = tid + s * 256;
            int kk = e & 31, l = e >> 5;
            Xs[l * 33 + kk] = Ib[(size_t)l * K + kc + kk];
        }
        __syncthreads();
#pragma unroll
        for (int kk = 0; kk < 32; kk++) {
            float w0 = Ws[kk * 129 + tc];
            float w1 = Ws[kk * 129 + tc + 32];
            float w2 = Ws[kk * 129 + tc + 64];
            float w3 = Ws[kk * 129 + tc + 96];
#pragma unroll
            for (int i = 0; i < 8; i++) {
                float xv = Xs[(tr * 8 + i) * 33 + kk];
                acc[i][0] = fmaf(xv, w0, acc[i][0]);
                acc[i][1] = fmaf(xv, w1, acc[i][1]);
                acc[i][2] = fmaf(xv, w2, acc[i][2]);
                acc[i][3] = fmaf(xv, w3, acc[i][3]);
            }
        }
        __syncthreads();
    }

#pragma unroll
    for (int s = 0; s < TT; s++) {
        float us[4];
#pragma unroll
        for (int d = 0; d < 4; d++)
            us[d] = U[(size_t)(b * TT + s) * N + nb * 128 + tc + 32 * d];
#pragma unroll
        for (int i = 0; i < 8; i++) {
            float cf = Cs[s][tr * 8 + i];
#pragma unroll
            for (int d = 0; d < 4; d++) acc[i][d] = fmaf(-cf, us[d], acc[i][d]);
        }
    }

    float bv[4] = {0.f, 0.f, 0.f, 0.f};
    if (LAYER != 4) {
        const float* bias = (LAYER == 1) ? g_b1 : (LAYER == 2) ? g_b2 : g_b3;
#pragma unroll
        for (int d = 0; d < 4; d++) bv[d] = bias[b * HH + nb * 128 + tc + 32 * d];
    }
    float* op = (LAYER == 4) ? outp : (LAYER == 1) ? g_ea : (LAYER == 2) ? g_eb : g_ea;
#pragma unroll
    for (int i = 0; i < 8; i++) {
        int l = lb * 64 + tr * 8 + i;
        size_t rowo = ((size_t)b * LL + l) * N + nb * 128;
#pragma unroll
        for (int d = 0; d < 4; d++) {
            float v = acc[i][d];
            if (LAYER != 4) v = fmaxf(v + bv[d], 0.f);
            if (LAYER == 3) v *= gate[((size_t)b * LL + l) * HH + nb * 128 + tc + 32 * d];
            op[rowo + tc + 32 * d] = v;
        }
    }
}

__global__ void k_loss(const float* __restrict__ ty, const float* __restrict__ loglr,
                       float* __restrict__ out) {
    int gw = (blockIdx.x * blockDim.x + threadIdx.x) >> 5;
    int lane = threadIdx.x & 31;
    if (gw >= BB * LL) return;
    const float* lg = out + 4097 + (size_t)gw * YY;
    const float* tyv = ty + (size_t)gw * YY;
    float acc = 0.f;
#pragma unroll
    for (int k = lane, it = 0; it < YY / 32; it++, k += 32) {
        float d = lg[k] - tyv[k];
        acc = fmaf(d, d, acc);
    }
    acc = warp_sum(acc);
    if (lane == 0) {
        float m = acc * (1.f / (float)YY);
        out[gw] = m;
        out[2049 + gw] = m;
    }
    if (gw == 0 && lane == 0) out[2048] = expf(*loglr);
}

extern "C" void kernel_launch(void* const* d_in, const int* in_sizes, int n_in,
                              void* d_out, int out_size) {
    const float* train_x = (const float*)d_in[0];
    const float* train_y = (const float*)d_in[1];
    const float* test_x = (const float*)d_in[2];
    const float* test_y = (const float*)d_in[3];
    const float* train_gate = (const float*)d_in[4];
    const float* test_gate = (const float*)d_in[5];
    const float* fc1 = (const float*)d_in[6];
    const float* b1 = (const float*)d_in[7];
    const float* fc2 = (const float*)d_in[8];
    const float* b2 = (const float*)d_in[9];
    const float* fc3 = (const float*)d_in[10];
    const float* b3 = (const float*)d_in[11];
    const float* fc4 = (const float*)d_in[12];
    const float* loglr = (const float*)d_in[13];
    float* out = (float*)d_out;

    k_tr<<<640, 256>>>(fc2, fc3, fc4);
    k_miscA<<<32, 256>>>(b1, b2, b3);
    k_miscB<<<64, 256>>>(train_x);
    k_train<<<64, TPB>>>(train_x, train_y, train_gate, fc1, fc2, fc3, fc4, loglr);

    k_cf<1><<<32, 256>>>(train_x, test_x, loglr);
    k_eval<1><<<BB * (HH / 128) * 2, 256>>>(test_x, nullptr, nullptr, fc1);
    k_cf<2><<<32, 256>>>(nullptr, nullptr, loglr);
    k_eval<2><<<BB * (HH / 128) * 2, 256>>>(nullptr, nullptr, nullptr, fc2);
    k_cf<3><<<32, 256>>>(nullptr, nullptr, loglr);
    k_eval<3><<<BB * (HH / 128) * 2, 256>>>(nullptr, test_gate, nullptr, fc3);
    k_cf<4><<<32, 256>>>(nullptr, nullptr, loglr);
    k_eval<4><<<BB * (YY / 128) * 2, 256>>>(nullptr, nullptr, out + 4097, fc4);

    k_loss<<<256, 256>>>(test_y, loglr, out);
}